// round 4
// baseline (speedup 1.0000x reference)
#include <cuda_runtime.h>

#define NR 32
#define NA 16
#define TPB 128        // 4 warps; warp w handles rules 8w..8w+7
#define SPB 64         // samples per block: 32 lanes * 2 samples

static __device__ __forceinline__ unsigned long long pack2(float lo, float hi) {
    unsigned long long r;
    asm("mov.b64 %0, {%1, %2};" : "=l"(r) : "f"(lo), "f"(hi));
    return r;
}
static __device__ __forceinline__ void unpack2(unsigned long long v, float& lo, float& hi) {
    asm("mov.b64 {%0, %1}, %2;" : "=f"(lo), "=f"(hi) : "l"(v));
}
static __device__ __forceinline__ unsigned long long fma2(
    unsigned long long a, unsigned long long b, unsigned long long c) {
    unsigned long long d;
    asm("fma.rn.f32x2 %0, %1, %2, %3;" : "=l"(d) : "l"(a), "l"(b), "l"(c));
    return d;
}
static __device__ __forceinline__ unsigned long long add2(
    unsigned long long a, unsigned long long b) {
    unsigned long long d;
    asm("add.rn.f32x2 %0, %1, %2;" : "=l"(d) : "l"(a), "l"(b));
    return d;
}
static __device__ __forceinline__ float ex2(float x) {
    float y;
    asm("ex2.approx.f32 %0, %1;" : "=f"(y) : "f"(x));
    return y;
}

__global__ __launch_bounds__(TPB, 6)
void tsk_kernel(const float* __restrict__ input,
                const float* __restrict__ frbw,
                const float* __restrict__ C,
                float* __restrict__ out, int B)
{
    // Packed coefficient records, 6 u64 slots per 2 k-steps:
    //   [0]=(p_e,p_e) [1]=(q_e,q_e) [2]=(c_e,c_e) [3]=(p_o,p_o) [4]=(q_o,q_o) [5]=(c_o,c_o)
    // Read as 3x LDS.128: (p_e|q_e), (c_e|p_o), (q_o|c_o) -> 1.5 LDS per k-step.
    // Every lane of a warp reads the SAME address -> 1 broadcast wavefront each.
    __shared__ unsigned long long s_co[4 * 8 * 48];   // [rulegroup][rule][8kk*6] = 12 KB
    __shared__ unsigned long long s_rc[NR];           // exponent const (dup pair)
    __shared__ unsigned long long s_c0[NR];           // C[r][0]        (dup pair)
    __shared__ float              s_ct[NR * NA];      // scratch for const reduction
    __shared__ ulonglong2         s_red[3][32];       // partials from warps 1..3

    const float L2E = 1.4426950408889634f;
    const int tid = threadIdx.x;

    // ---- coefficient precompute (4 iters/thread) ----
    for (int i = tid; i < NR * NA; i += TPB) {
        // Faithful to reference: idx=r*A+k; (sigma,center)=FRB_W[idx],FRB_W[idx+1]
        float sig = frbw[i];
        float cen = frbw[i + 1];
        float is2 = 1.0f / (sig * sig);
        float p = -0.5f * is2 * L2E;
        float q = is2 * cen * L2E;
        int r = i >> 4, k = i & 15;
        float c = C[r * (NA + 1) + k + 1];
        int rg = r >> 3, j = r & 7, kk = k >> 1, par = k & 1;
        unsigned long long* slot = s_co + rg * 384 + j * 48 + kk * 6 + par * 3;
        slot[0] = pack2(p, p);
        slot[1] = pack2(q, q);
        slot[2] = pack2(c, c);
        s_ct[i] = p * cen * cen;   // -0.5*(cen/sig)^2 * log2e
    }
    __syncthreads();
    if (tid < NR) {
        float acc = 0.0f;
        #pragma unroll
        for (int k = 0; k < NA; k++) acc += s_ct[tid * NA + k];
        s_rc[tid] = pack2(acc, acc);
        float c0 = C[tid * (NA + 1)];
        s_c0[tid] = pack2(c0, c0);
    }
    __syncthreads();

    // ---- mapping: warp w = rule group, lane = sample pair ----
    const int w    = tid >> 5;
    const int lane = tid & 31;
    const int s0   = blockIdx.x * SPB + lane * 2;

    int r0 = s0,     r1 = s0 + 1;
    if (r0 >= B) r0 = B - 1;
    if (r1 >= B) r1 = B - 1;

    const float4* in4 = (const float4*)input;
    unsigned long long X[NA];
    #pragma unroll
    for (int j = 0; j < 4; j++) {
        float4 a = in4[r0 * 4 + j];
        float4 b = in4[r1 * 4 + j];
        X[j * 4 + 0] = pack2(a.x, b.x);
        X[j * 4 + 1] = pack2(a.y, b.y);
        X[j * 4 + 2] = pack2(a.z, b.z);
        X[j * 4 + 3] = pack2(a.w, b.w);
    }

    const ulonglong2* co = (const ulonglong2*)(s_co + w * 384);
    const int rbase = w * 8;

    unsigned long long num = 0ull, den = 0ull;

    #pragma unroll 2            // body ~2x80 instrs, stays in L0 I$
    for (int j = 0; j < 8; j++) {
        unsigned long long e  = s_rc[rbase + j];
        unsigned long long ch = s_c0[rbase + j];
        const ulonglong2* rec = co + j * 24;
        #pragma unroll
        for (int kk = 0; kk < 8; kk++) {
            ulonglong2 w0 = rec[kk * 3 + 0];   // (p_e | q_e)
            ulonglong2 w1 = rec[kk * 3 + 1];   // (c_e | p_o)
            ulonglong2 w2 = rec[kk * 3 + 2];   // (q_o | c_o)
            unsigned long long xe = X[kk * 2], xo = X[kk * 2 + 1];
            unsigned long long t0 = fma2(w0.x, xe, w0.y);
            unsigned long long t1 = fma2(w1.y, xo, w2.x);
            e  = fma2(t0, xe, e);
            ch = fma2(w1.x, xe, ch);
            e  = fma2(t1, xo, e);
            ch = fma2(w2.y, xo, ch);
        }
        float e0, e1;
        unpack2(e, e0, e1);
        unsigned long long u = pack2(ex2(e0), ex2(e1));
        num = fma2(u, ch, num);
        den = add2(den, u);
    }

    // ---- combine the 4 rule-group warps ----
    if (w != 0) s_red[w - 1][lane] = make_ulonglong2(num, den);
    __syncthreads();
    if (w == 0 && s0 < B) {
        #pragma unroll
        for (int i = 0; i < 3; i++) {
            ulonglong2 p = s_red[i][lane];
            num = add2(num, p.x);
            den = add2(den, p.y);
        }
        float n0, n1, d0, d1;
        unpack2(num, n0, n1);
        unpack2(den, d0, d1);
        if (s0 + 1 < B) {
            *(float2*)(out + s0) = make_float2(__fdividef(n0, d0), __fdividef(n1, d1));
        } else {
            out[s0] = __fdividef(n0, d0);
        }
    }
}

extern "C" void kernel_launch(void* const* d_in, const int* in_sizes, int n_in,
                              void* d_out, int out_size)
{
    const float* input = (const float*)d_in[0];   // [B, 16] fp32
    const float* frbw  = (const float*)d_in[1];   // [1024]  fp32
    const float* Cm    = (const float*)d_in[2];   // [32,17] fp32
    float* out = (float*)d_out;                   // [B]     fp32

    int B = in_sizes[0] / NA;
    int blocks = (B + SPB - 1) / SPB;             // 1024 blocks for B=65536
    tsk_kernel<<<blocks, TPB>>>(input, frbw, Cm, out, B);
}

// round 5
// speedup vs baseline: 1.1175x; 1.1175x over previous
#include <cuda_runtime.h>

#define NR 32
#define NA 16
#define TPB 128        // 4 warps: half = w>>1 selects rules, grp = w&1 selects samples
#define SPB 128        // samples per block: 64 threads-per-half * 2 samples

static __device__ __forceinline__ unsigned long long pack2(float lo, float hi) {
    unsigned long long r;
    asm("mov.b64 %0, {%1, %2};" : "=l"(r) : "f"(lo), "f"(hi));
    return r;
}
static __device__ __forceinline__ void unpack2(unsigned long long v, float& lo, float& hi) {
    asm("mov.b64 {%0, %1}, %2;" : "=f"(lo), "=f"(hi) : "l"(v));
}
static __device__ __forceinline__ unsigned long long fma2(
    unsigned long long a, unsigned long long b, unsigned long long c) {
    unsigned long long d;
    asm("fma.rn.f32x2 %0, %1, %2, %3;" : "=l"(d) : "l"(a), "l"(b), "l"(c));
    return d;
}
static __device__ __forceinline__ unsigned long long add2(
    unsigned long long a, unsigned long long b) {
    unsigned long long d;
    asm("add.rn.f32x2 %0, %1, %2;" : "=l"(d) : "l"(a), "l"(b));
    return d;
}
static __device__ __forceinline__ float ex2(float x) {
    float y;
    asm("ex2.approx.f32 %0, %1;" : "=f"(y) : "f"(x));
    return y;
}

// One record = 2 k-steps = 3 ulonglong2:
//   rec[0] = (p_e,p_e | q_e,q_e)   rec[1] = (c_e,c_e | p_o,p_o)   rec[2] = (q_o,q_o | c_o,c_o)
// 16 rules * 8 records per half, +4 pad records so the prefetch never goes OOB.
#define RECS_PER_HALF (16 * 8)
#define HALF_STRIDE   ((RECS_PER_HALF + 4) * 3)   // in ulonglong2 units

__global__ __launch_bounds__(TPB, 4)
void tsk_kernel(const float* __restrict__ input,
                const float* __restrict__ frbw,
                const float* __restrict__ C,
                float* __restrict__ out, int B)
{
    __shared__ ulonglong2         s_co[2 * HALF_STRIDE];  // ~12.4 KB coefficient stream
    __shared__ unsigned long long s_rc[NR];               // exponent const (dup pair)
    __shared__ unsigned long long s_c0[NR];               // C[r][0]        (dup pair)
    __shared__ float              s_ct[NR * NA];          // scratch
    __shared__ ulonglong2         s_red[64];              // (num,den) partials from half 1

    const float L2E = 1.4426950408889634f;
    const int tid = threadIdx.x;

    // ---- coefficient precompute (once per block) ----
    for (int i = tid; i < NR * NA; i += TPB) {
        // Faithful to reference: idx=r*A+k; (sigma,center)=FRB_W[idx],FRB_W[idx+1]
        float sig = frbw[i];
        float cen = frbw[i + 1];
        float is2 = 1.0f / (sig * sig);
        float p = -0.5f * is2 * L2E;
        float q = is2 * cen * L2E;
        int r = i >> 4, k = i & 15;
        float c = C[r * (NA + 1) + k + 1];
        int half = r >> 4, j = r & 15, kk = k >> 1, par = k & 1;
        // u64 view of the record: slots 0..5 = p_e,q_e,c_e,p_o,q_o,c_o
        unsigned long long* slot =
            (unsigned long long*)(s_co + half * HALF_STRIDE + (j * 8 + kk) * 3) + par * 3;
        slot[0] = pack2(p, p);
        slot[1] = pack2(q, q);
        slot[2] = pack2(c, c);
        s_ct[i] = p * cen * cen;   // -0.5*(cen/sig)^2 * log2e
    }
    __syncthreads();
    if (tid < NR) {
        float acc = 0.0f;
        #pragma unroll
        for (int k = 0; k < NA; k++) acc += s_ct[tid * NA + k];
        s_rc[tid] = pack2(acc, acc);
        float c0 = C[tid * (NA + 1)];
        s_c0[tid] = pack2(c0, c0);
    }
    __syncthreads();

    // ---- mapping: warp pair -> rule half; 64 threads -> 64 sample pairs ----
    const int w    = tid >> 5;
    const int half = w >> 1;          // 0: rules 0-15, 1: rules 16-31
    const int t    = tid & 63;        // sample-pair slot in block
    const int s0   = blockIdx.x * SPB + t * 2;

    int r0 = s0, r1 = s0 + 1;
    if (r0 >= B) r0 = B - 1;
    if (r1 >= B) r1 = B - 1;

    const float4* in4 = (const float4*)input;
    unsigned long long X[NA];
    #pragma unroll
    for (int j = 0; j < 4; j++) {
        float4 a = in4[r0 * 4 + j];
        float4 b = in4[r1 * 4 + j];
        X[j * 4 + 0] = pack2(a.x, b.x);
        X[j * 4 + 1] = pack2(a.y, b.y);
        X[j * 4 + 2] = pack2(a.z, b.z);
        X[j * 4 + 3] = pack2(a.w, b.w);
    }

    const ulonglong2* co = s_co + half * HALF_STRIDE;   // all lanes same addr -> broadcast
    const int rbase = half * 16;

    // ---- 4-deep software pipeline: prefetch record i+4 while computing i ----
    ulonglong2 buf[4][3];
    #pragma unroll
    for (int i = 0; i < 4; i++) {
        buf[i][0] = co[i * 3 + 0];
        buf[i][1] = co[i * 3 + 1];
        buf[i][2] = co[i * 3 + 2];
    }

    unsigned long long num = 0ull, den = 0ull;

    #pragma unroll 1
    for (int j = 0; j < 16; j++) {
        unsigned long long e  = s_rc[rbase + j];
        unsigned long long ch = s_c0[rbase + j];
        const ulonglong2* nxt = co + (j * 8 + 4) * 3;   // prefetch source (pad makes it safe)
        #pragma unroll
        for (int kk = 0; kk < 8; kk++) {
            const int slot = kk & 3;
            ulonglong2 w0 = buf[slot][0];   // (p_e | q_e)
            ulonglong2 w1 = buf[slot][1];   // (c_e | p_o)
            ulonglong2 w2 = buf[slot][2];   // (q_o | c_o)
            // prefetch record (j*8 + kk + 4) into the slot just freed
            buf[slot][0] = nxt[kk * 3 + 0];
            buf[slot][1] = nxt[kk * 3 + 1];
            buf[slot][2] = nxt[kk * 3 + 2];
            unsigned long long xe = X[kk * 2], xo = X[kk * 2 + 1];
            unsigned long long t0 = fma2(w0.x, xe, w0.y);
            unsigned long long t1 = fma2(w1.y, xo, w2.x);
            e  = fma2(t0, xe, e);
            ch = fma2(w1.x, xe, ch);
            e  = fma2(t1, xo, e);
            ch = fma2(w2.y, xo, ch);
        }
        float e0, e1;
        unpack2(e, e0, e1);
        unsigned long long u = pack2(ex2(e0), ex2(e1));
        num = fma2(u, ch, num);
        den = add2(den, u);
    }

    // ---- combine the two rule halves ----
    if (half == 1) s_red[t] = make_ulonglong2(num, den);
    __syncthreads();
    if (half == 0 && s0 < B) {
        ulonglong2 p = s_red[t];
        num = add2(num, p.x);
        den = add2(den, p.y);
        float n0, n1, d0, d1;
        unpack2(num, n0, n1);
        unpack2(den, d0, d1);
        if (s0 + 1 < B) {
            *(float2*)(out + s0) = make_float2(__fdividef(n0, d0), __fdividef(n1, d1));
        } else {
            out[s0] = __fdividef(n0, d0);
        }
    }
}

extern "C" void kernel_launch(void* const* d_in, const int* in_sizes, int n_in,
                              void* d_out, int out_size)
{
    const float* input = (const float*)d_in[0];   // [B, 16] fp32
    const float* frbw  = (const float*)d_in[1];   // [1024]  fp32
    const float* Cm    = (const float*)d_in[2];   // [32,17] fp32
    float* out = (float*)d_out;                   // [B]     fp32

    int B = in_sizes[0] / NA;
    int blocks = (B + SPB - 1) / SPB;             // 512 blocks for B=65536
    tsk_kernel<<<blocks, TPB>>>(input, frbw, Cm, out, B);
}